// round 9
// baseline (speedup 1.0000x reference)
#include <cuda_runtime.h>
#include <cuda_fp16.h>
#include <cstdint>

// ----------------------------------------------------------------------------
// Problem constants
// ----------------------------------------------------------------------------
#define B_   8192
#define T_   137
#define D_   384
#define K_   128
#define BM   128
#define NF   (B_*D_)
#define NW   (T_*K_*D_)
#define NBT  (B_/BM)              // 64 b-tiles
#define NTILES (NBT*T_)           // 8768 tiles; tile = t*64 + btile

#define DCHUNK 64
#define NCH    (D_/DCHUNK)        // 6
#define STAGES 3

#define TILE_BYTES  16384         // 128 rows x 128B (64 fp16)
#define STAGE_BYTES (2*TILE_BYTES)                 // A, B
#define OFF_CONST   (STAGES*STAGE_BYTES)           // 98304
#define OFF_RED     (OFF_CONST + 3*128*4)
#define SMEM_TOTAL  (OFF_RED + 128*4*4)            // 101,888 B -> 2 CTAs/SM

// ----------------------------------------------------------------------------
// fp16 scratch (device globals; no allocation allowed)
// ----------------------------------------------------------------------------
__device__ __align__(16) __half g_f_h[NF];
__device__ __align__(16) __half g_w_h[NW];

// ----------------------------------------------------------------------------
// helpers
// ----------------------------------------------------------------------------
__device__ __forceinline__ uint32_t smem_u32(const void* p) {
    uint32_t a;
    asm("{ .reg .u64 t; cvta.to.shared.u64 t, %1; cvt.u32.u64 %0, t; }"
        : "=r"(a) : "l"(p));
    return a;
}
__device__ __forceinline__ void cp16(uint32_t saddr, const void* g) {
    asm volatile("cp.async.cg.shared.global [%0], [%1], 16;"
                 :: "r"(saddr), "l"(g) : "memory");
}
template <int N>
__device__ __forceinline__ void cp_wait() {
    asm volatile("cp.async.wait_group %0;" :: "n"(N) : "memory");
}
__device__ __forceinline__ void cp_commit() {
    asm volatile("cp.async.commit_group;" ::: "memory");
}
__device__ __forceinline__ void ldsm4(uint32_t* r, uint32_t addr) {
    asm volatile("ldmatrix.sync.aligned.m8n8.x4.shared.b16 {%0,%1,%2,%3}, [%4];"
                 : "=r"(r[0]), "=r"(r[1]), "=r"(r[2]), "=r"(r[3]) : "r"(addr));
}
__device__ __forceinline__ void mma_f16(float* c, const uint32_t* a,
                                        const uint32_t b0, const uint32_t b1) {
    asm volatile(
        "mma.sync.aligned.m16n8k16.row.col.f32.f16.f16.f32 "
        "{%0,%1,%2,%3}, {%4,%5,%6,%7}, {%8,%9}, {%0,%1,%2,%3};"
        : "+f"(c[0]), "+f"(c[1]), "+f"(c[2]), "+f"(c[3])
        : "r"(a[0]), "r"(a[1]), "r"(a[2]), "r"(a[3]), "r"(b0), "r"(b1));
}
__device__ __forceinline__ uint32_t swz128(uint32_t o) {
    return o ^ ((o >> 3) & 0x70);
}

// ----------------------------------------------------------------------------
// Pre-pass: f, W1 -> fp16 (round-to-nearest)
// ----------------------------------------------------------------------------
__global__ void __launch_bounds__(256)
split_kernel(const float* __restrict__ f, const float* __restrict__ w1)
{
    const size_t NF4 = NF / 4, NT = NF4 + NW / 4;
    size_t i = (size_t)blockIdx.x * blockDim.x + threadIdx.x;
    if (i >= NT) return;

    float4 v;
    uint2* dst;
    if (i < NF4) {
        v = ((const float4*)f)[i];
        dst = (uint2*)g_f_h + i;
    } else {
        size_t j = i - NF4;
        v = ((const float4*)w1)[j];
        dst = (uint2*)g_w_h + j;
    }
    __half2 h01 = __halves2half2(__float2half_rn(v.x), __float2half_rn(v.y));
    __half2 h23 = __halves2half2(__float2half_rn(v.z), __float2half_rn(v.w));
    uint2 u;
    u.x = *reinterpret_cast<uint32_t*>(&h01);
    u.y = *reinterpret_cast<uint32_t*>(&h23);
    *dst = u;
}

// ----------------------------------------------------------------------------
// Main kernel: persistent CTAs; each strides over (b-tile, head) tiles.
// Per tile: GEMM 128x128x384 (fp16, mma.sync) + BN + LReLU + dot(W2).
// cp.async pipeline runs continuously across tile boundaries.
// ----------------------------------------------------------------------------
__global__ void __launch_bounds__(256, 2)
heads_mma_kernel(const float* __restrict__ b1,
                 const float* __restrict__ gamma,
                 const float* __restrict__ beta,
                 const float* __restrict__ rmean,
                 const float* __restrict__ rvar,
                 const float* __restrict__ W2,
                 const float* __restrict__ b2,
                 float* __restrict__ out)
{
    extern __shared__ char sm[];
    const uint32_t smem_base = smem_u32(sm);

    const int tid  = threadIdx.x;
    const int warp = tid >> 5;
    const int lane = tid & 31;
    const int wm   = warp & 1;       // M group (2 x 64 rows)
    const int wn   = warp >> 1;      // N group (4 x 32 cols)
    const int stride = gridDim.x;

    float* sc_s = (float*)(sm + OFF_CONST);
    float* cc_s = sc_s + 128;
    float* w2_s = sc_s + 256;
    float* red  = (float*)(sm + OFF_RED);     // [128][4]

    // per-thread cp.async mapping: 4 x 16B chunks per 128x64 tile
    uint32_t sofs[4];
    int      gofs[4];
#pragma unroll
    for (int q = 0; q < 4; q++) {
        const int idx = q * 256 + tid;
        const int row = idx >> 3;
        const int seg = idx & 7;
        sofs[q] = swz128((uint32_t)(row * 128 + seg * 16));
        gofs[q] = row * D_ + seg * 8;
    }

#define ISSUE(pA, pB, c) do {                                                \
    const uint32_t _sb = smem_base + ((c) % STAGES) * STAGE_BYTES;           \
    _Pragma("unroll")                                                        \
    for (int q = 0; q < 4; q++)                                              \
        cp16(_sb + sofs[q], (pA) + gofs[q] + (c) * DCHUNK);                  \
    _Pragma("unroll")                                                        \
    for (int q = 0; q < 4; q++)                                              \
        cp16(_sb + TILE_BYTES + sofs[q], (pB) + gofs[q] + (c) * DCHUNK);     \
    cp_commit();                                                             \
} while (0)

#define LOAD_CONSTS(tt) do {                                                 \
    if (tid < 128) {                                                         \
        const int _k = (tt) * K_ + tid;                                      \
        const float _sc = gamma[_k] * rsqrtf(rvar[_k] + 1e-5f);              \
        sc_s[tid] = _sc;                                                     \
        cc_s[tid] = (b1[_k] - rmean[_k]) * _sc + beta[_k];                   \
        w2_s[tid] = W2[_k];                                                  \
    }                                                                        \
} while (0)

    int tile = blockIdx.x;
    const __half* srcA = g_f_h + (size_t)(tile & 63) * (BM * D_);
    const __half* srcB = g_w_h + (size_t)(tile >> 6) * (K_ * D_);

    // prologue: 2 chunks of the first tile in flight
    ISSUE(srcA, srcB, 0);
    ISSUE(srcA, srcB, 1);
    LOAD_CONSTS(tile >> 6);

    // ldmatrix address pre-computation (stage-relative, tile-invariant)
    const int grp = lane >> 3;
    const int lr  = lane & 7;
    const uint32_t xorv = (uint32_t)(lr << 4);
    const uint32_t aHi  = (uint32_t)((grp >> 1) * 16);
    const uint32_t bHi  = (uint32_t)((grp & 1) * 16);
    const uint32_t aRow = (uint32_t)((wm * 64 + (grp & 1) * 8 + lr) * 128);
    const uint32_t bRow = (uint32_t)((wn * 32 + (grp >> 1) * 8 + lr) * 128);
    const uint32_t aBase = smem_base + aRow;
    const uint32_t bBase = smem_base + TILE_BYTES + bRow;

#define KSTEP(stOfs, ks) do {                                                \
    uint32_t af[4][4], bf[2][4];                                             \
    const uint32_t _ca = ((uint32_t)((ks) * 32) + aHi) ^ xorv;               \
    const uint32_t _cb = ((uint32_t)((ks) * 32) + bHi) ^ xorv;               \
    ldsm4(bf[0], bBase + (stOfs) + _cb);                                     \
    ldsm4(bf[1], bBase + (stOfs) + 2048u + _cb);                             \
    ldsm4(af[0], aBase + (stOfs) + _ca);                                     \
    _Pragma("unroll")                                                        \
    for (int mi = 0; mi < 4; mi++) {                                         \
        if (mi < 3)                                                          \
            ldsm4(af[mi + 1], aBase + (stOfs) + (uint32_t)((mi + 1) * 2048) + _ca); \
        _Pragma("unroll")                                                    \
        for (int ni = 0; ni < 4; ni++) {                                     \
            const int nf = ni >> 1, p = (ni & 1) * 2;                        \
            mma_f16(acc[mi][ni], af[mi], bf[nf][p], bf[nf][p + 1]);          \
        }                                                                    \
    }                                                                        \
} while (0)

#define CHUNK_BODY(c) do {                                                   \
    const uint32_t _ofs = (uint32_t)(((c) % STAGES) * STAGE_BYTES);          \
    KSTEP(_ofs, 0); KSTEP(_ofs, 1); KSTEP(_ofs, 2); KSTEP(_ofs, 3);          \
} while (0)

    float acc[4][4][4];

    for (;;) {
        int nt = tile + stride;
        const bool last = (nt >= NTILES);
        if (last) nt = tile;                    // dummy prefetch target

#pragma unroll
        for (int mi = 0; mi < 4; mi++)
#pragma unroll
            for (int ni = 0; ni < 4; ni++)
#pragma unroll
                for (int r = 0; r < 4; r++) acc[mi][ni][r] = 0.0f;

        // Stage map per tile: chunks 0..5 -> stages 0,1,2,0,1,2. The barrier
        // at chunk c orders all reads of the stage ISSUE(c+2) overwrites.
        cp_wait<1>(); __syncthreads(); ISSUE(srcA, srcB, 2); CHUNK_BODY(0);
        cp_wait<1>(); __syncthreads(); ISSUE(srcA, srcB, 3); CHUNK_BODY(1);
        cp_wait<1>(); __syncthreads(); ISSUE(srcA, srcB, 4); CHUNK_BODY(2);
        cp_wait<1>(); __syncthreads(); ISSUE(srcA, srcB, 5); CHUNK_BODY(3);
        {   // next tile's chunk 0 (recompute pointers inline: short liveness)
            const __half* nA = g_f_h + (size_t)(nt & 63) * (BM * D_);
            const __half* nB = g_w_h + (size_t)(nt >> 6) * (K_ * D_);
            cp_wait<1>(); __syncthreads(); ISSUE(nA, nB, 0); CHUNK_BODY(4);
            cp_wait<1>(); __syncthreads(); ISSUE(nA, nB, 1); CHUNK_BODY(5);
            srcA = nA; srcB = nB;
        }

        // ------------------------- epilogue (per tile) -------------------
        const int b0 = (tile & 63) * BM;
        const int t  = tile >> 6;

        float scr[8], ccr[8], w2r[8];
#pragma unroll
        for (int ni = 0; ni < 4; ni++)
#pragma unroll
            for (int j = 0; j < 2; j++) {
                const int k = wn * 32 + ni * 8 + (lane & 3) * 2 + j;
                scr[ni * 2 + j] = sc_s[k];
                ccr[ni * 2 + j] = cc_s[k];
                w2r[ni * 2 + j] = w2_s[k];
            }

#pragma unroll
        for (int mi = 0; mi < 4; mi++) {
#pragma unroll
            for (int h = 0; h < 2; h++) {
                float s = 0.0f;
#pragma unroll
                for (int ni = 0; ni < 4; ni++) {
#pragma unroll
                    for (int j = 0; j < 2; j++) {
                        float y = fmaf(acc[mi][ni][h * 2 + j],
                                       scr[ni * 2 + j], ccr[ni * 2 + j]);
                        y = fmaxf(y, 0.01f * y);          // LeakyReLU
                        s = fmaf(y, w2r[ni * 2 + j], s);
                    }
                }
                s += __shfl_xor_sync(0xffffffffu, s, 1);
                s += __shfl_xor_sync(0xffffffffu, s, 2);
                if ((lane & 3) == 0) {
                    const int row = wm * 64 + mi * 16 + h * 8 + (lane >> 2);
                    red[row * 4 + wn] = s;
                }
            }
        }
        __syncthreads();      // red ready; also: all const reads are done

        if (tid < 128) {
            const float s = red[tid * 4 + 0] + red[tid * 4 + 1]
                          + red[tid * 4 + 2] + red[tid * 4 + 3] + b2[t];
            out[(size_t)(b0 + tid) * T_ + t] = s;
        }

        if (last) break;
        tile = nt;
        LOAD_CONSTS(tile >> 6);   // safe: after red-barrier, before next epilogue
    }
#undef ISSUE
#undef LOAD_CONSTS
#undef KSTEP
#undef CHUNK_BODY
}

// ----------------------------------------------------------------------------
// launch
// ----------------------------------------------------------------------------
extern "C" void kernel_launch(void* const* d_in, const int* in_sizes, int n_in,
                              void* d_out, int out_size)
{
    const float* f     = (const float*)d_in[0];
    const float* W1    = (const float*)d_in[1];
    const float* b1    = (const float*)d_in[2];
    const float* gamma = (const float*)d_in[3];
    const float* beta  = (const float*)d_in[4];
    const float* rmean = (const float*)d_in[5];
    const float* rvar  = (const float*)d_in[6];
    const float* W2    = (const float*)d_in[7];
    const float* b2    = (const float*)d_in[8];
    float* out = (float*)d_out;

    {
        const size_t total4 = (size_t)NF / 4 + (size_t)NW / 4;
        const int blocks = (int)((total4 + 255) / 256);
        split_kernel<<<blocks, 256>>>(f, W1);
    }

    int nsm = 148;
    cudaDeviceGetAttribute(&nsm, cudaDevAttrMultiProcessorCount, 0);

    cudaFuncSetAttribute(heads_mma_kernel,
                         cudaFuncAttributeMaxDynamicSharedMemorySize, SMEM_TOTAL);
    dim3 grid(2 * nsm);    // persistent: 2 CTAs per SM
    heads_mma_kernel<<<grid, 256, SMEM_TOTAL>>>(b1, gamma, beta, rmean, rvar,
                                                W2, b2, out);
}

// round 10
// speedup vs baseline: 1.0708x; 1.0708x over previous
#include <cuda_runtime.h>
#include <cuda_fp16.h>
#include <cstdint>

// ----------------------------------------------------------------------------
// Problem constants
// ----------------------------------------------------------------------------
#define B_   8192
#define T_   137
#define D_   384
#define K_   128
#define BM   128
#define NF   (B_*D_)
#define NW   (T_*K_*D_)

#define DCHUNK 64
#define NCH    (D_/DCHUNK)        // 6
#define STAGES 3

#define TILE_BYTES  16384         // 128 rows x 128B (64 fp16)
#define STAGE_BYTES (2*TILE_BYTES)                 // A, B
#define OFF_MBAR    (STAGES*STAGE_BYTES)           // 98304: full[3], empty[3]
#define OFF_CONST   (OFF_MBAR + 64)                // 98368: sc,cc,w2 [128] each
#define OFF_RED     (OFF_CONST + 3*128*4)          // 99904
#define SMEM_TOTAL  (OFF_RED + 128*4*4)            // 101,952 B -> 2 CTAs/SM

// ----------------------------------------------------------------------------
// fp16 scratch (device globals; no allocation allowed)
// ----------------------------------------------------------------------------
__device__ __align__(16) __half g_f_h[NF];
__device__ __align__(16) __half g_w_h[NW];

// ----------------------------------------------------------------------------
// helpers
// ----------------------------------------------------------------------------
__device__ __forceinline__ uint32_t smem_u32(const void* p) {
    uint32_t a;
    asm("{ .reg .u64 t; cvta.to.shared.u64 t, %1; cvt.u32.u64 %0, t; }"
        : "=r"(a) : "l"(p));
    return a;
}
__device__ __forceinline__ void cp16(uint32_t saddr, const void* g) {
    asm volatile("cp.async.cg.shared.global [%0], [%1], 16;"
                 :: "r"(saddr), "l"(g) : "memory");
}
__device__ __forceinline__ void ldsm4(uint32_t* r, uint32_t addr) {
    asm volatile("ldmatrix.sync.aligned.m8n8.x4.shared.b16 {%0,%1,%2,%3}, [%4];"
                 : "=r"(r[0]), "=r"(r[1]), "=r"(r[2]), "=r"(r[3]) : "r"(addr));
}
__device__ __forceinline__ void mma_f16(float* c, const uint32_t* a,
                                        const uint32_t b0, const uint32_t b1) {
    asm volatile(
        "mma.sync.aligned.m16n8k16.row.col.f32.f16.f16.f32 "
        "{%0,%1,%2,%3}, {%4,%5,%6,%7}, {%8,%9}, {%0,%1,%2,%3};"
        : "+f"(c[0]), "+f"(c[1]), "+f"(c[2]), "+f"(c[3])
        : "r"(a[0]), "r"(a[1]), "r"(a[2]), "r"(a[3]), "r"(b0), "r"(b1));
}
__device__ __forceinline__ uint32_t swz128(uint32_t o) {
    return o ^ ((o >> 3) & 0x70);
}

#define MBAR_INIT(a, n) \
    asm volatile("mbarrier.init.shared.b64 [%0], %1;" :: "r"(a), "r"(n) : "memory")
#define MBAR_ARRIVE(a) \
    asm volatile("mbarrier.arrive.shared.b64 _, [%0];" :: "r"(a) : "memory")
#define CP_ARRIVE(a) \
    asm volatile("cp.async.mbarrier.arrive.noinc.shared.b64 [%0];" :: "r"(a) : "memory")
#define MBAR_WAIT(a, ph) do {                                                  \
    uint32_t _m = (a), _p = (ph), _d;                                          \
    asm volatile("{\n\t.reg .pred p;\n\t"                                      \
        "mbarrier.try_wait.parity.acquire.cta.shared::cta.b64 p, [%1], %2;\n\t"\
        "selp.b32 %0, 1, 0, p;\n\t}" : "=r"(_d) : "r"(_m), "r"(_p) : "memory");\
    if (!_d) {                                                                 \
        asm volatile("{\n\t.reg .pred P1;\n\tWL_%=:\n\t"                       \
            "mbarrier.try_wait.parity.acquire.cta.shared::cta.b64 P1, [%0], %1, 0x989680;\n\t" \
            "@P1 bra.uni WD_%=;\n\tbra.uni WL_%=;\n\tWD_%=:\n\t}"              \
            :: "r"(_m), "r"(_p) : "memory");                                   \
    }                                                                          \
} while (0)

// ----------------------------------------------------------------------------
// Pre-pass: f, W1 -> fp16 (round-to-nearest)
// ----------------------------------------------------------------------------
__global__ void __launch_bounds__(256)
split_kernel(const float* __restrict__ f, const float* __restrict__ w1)
{
    const size_t NF4 = NF / 4, NT = NF4 + NW / 4;
    size_t i = (size_t)blockIdx.x * blockDim.x + threadIdx.x;
    if (i >= NT) return;

    float4 v;
    uint2* dst;
    if (i < NF4) {
        v = ((const float4*)f)[i];
        dst = (uint2*)g_f_h + i;
    } else {
        size_t j = i - NF4;
        v = ((const float4*)w1)[j];
        dst = (uint2*)g_w_h + j;
    }
    __half2 h01 = __halves2half2(__float2half_rn(v.x), __float2half_rn(v.y));
    __half2 h23 = __halves2half2(__float2half_rn(v.z), __float2half_rn(v.w));
    uint2 u;
    u.x = *reinterpret_cast<uint32_t*>(&h01);
    u.y = *reinterpret_cast<uint32_t*>(&h23);
    *dst = u;
}

// ----------------------------------------------------------------------------
// Main kernel: 128x128x384 GEMM (fp16) + BN + LReLU + dot(W2).
// mbarrier producer/consumer pipeline: NO __syncthreads in the mainloop.
// ----------------------------------------------------------------------------
__global__ void __launch_bounds__(256, 2)
heads_mma_kernel(const float* __restrict__ b1,
                 const float* __restrict__ gamma,
                 const float* __restrict__ beta,
                 const float* __restrict__ rmean,
                 const float* __restrict__ rvar,
                 const float* __restrict__ W2,
                 const float* __restrict__ b2,
                 float* __restrict__ out)
{
    extern __shared__ char sm[];
    const uint32_t smem_base = smem_u32(sm);

    const int tid  = threadIdx.x;
    const int warp = tid >> 5;
    const int lane = tid & 31;
    const int wm   = warp & 1;       // M group (2 x 64 rows)
    const int wn   = warp >> 1;      // N group (4 x 32 cols)

    const int b0 = blockIdx.x * BM;
    const int t  = blockIdx.y;

    float* sc_s = (float*)(sm + OFF_CONST);
    float* cc_s = sc_s + 128;
    float* w2_s = sc_s + 256;
    float* red  = (float*)(sm + OFF_RED);     // [128][4]

    // mbarrier addresses: full[s] at +s*8, empty[s] at +24+s*8
    const uint32_t mbF = smem_base + OFF_MBAR;
    const uint32_t mbE = smem_base + OFF_MBAR + 24;

    if (tid == 0) {
#pragma unroll
        for (int s = 0; s < 3; s++) {
            MBAR_INIT(mbF + s * 8, 256);
            MBAR_INIT(mbE + s * 8, 256);
        }
    }
    if (tid < 128) {
        const int k = t * K_ + tid;
        const float sc = gamma[k] * rsqrtf(rvar[k] + 1e-5f);
        sc_s[tid] = sc;
        cc_s[tid] = (b1[k] - rmean[k]) * sc + beta[k];
        w2_s[tid] = W2[k];
    }
    __syncthreads();   // barriers + consts visible before any use

    // global tile sources: [A, B], row-major D_=384 cols
    const __half* srcA = g_f_h + (size_t)b0 * D_;
    const __half* srcB = g_w_h + (size_t)t * (K_ * D_);

    // per-thread cp.async mapping: 4 x 16B chunks per tile
    uint32_t sofs[4];
    int      gofs[4];
#pragma unroll
    for (int q = 0; q < 4; q++) {
        const int idx = q * 256 + tid;
        const int row = idx >> 3;
        const int seg = idx & 7;
        sofs[q] = swz128((uint32_t)(row * 128 + seg * 16));
        gofs[q] = row * D_ + seg * 8;
    }

    // ISSUE chunk c: 8 cp.async + completion-arrive on full[c%3]
#define ISSUE(c) do {                                                        \
    const uint32_t _sb = smem_base + ((c) % STAGES) * STAGE_BYTES;           \
    _Pragma("unroll")                                                        \
    for (int q = 0; q < 4; q++)                                              \
        cp16(_sb + sofs[q], srcA + gofs[q] + (c) * DCHUNK);                  \
    _Pragma("unroll")                                                        \
    for (int q = 0; q < 4; q++)                                              \
        cp16(_sb + TILE_BYTES + sofs[q], srcB + gofs[q] + (c) * DCHUNK);     \
    CP_ARRIVE(mbF + ((c) % STAGES) * 8);                                     \
} while (0)

    // prologue: two chunks in flight
    ISSUE(0); ISSUE(1);

    // ldmatrix address pre-computation
    const int grp = lane >> 3;
    const int lr  = lane & 7;
    const uint32_t xorv = (uint32_t)(lr << 4);
    const uint32_t aHi  = (uint32_t)((grp >> 1) * 16);
    const uint32_t bHi  = (uint32_t)((grp & 1) * 16);
    const uint32_t aRow = (uint32_t)((wm * 64 + (grp & 1) * 8 + lr) * 128);
    const uint32_t bRow = (uint32_t)((wn * 32 + (grp >> 1) * 8 + lr) * 128);
    const uint32_t aBase = smem_base + aRow;
    const uint32_t bBase = smem_base + TILE_BYTES + bRow;

    float acc[4][4][4];
#pragma unroll
    for (int mi = 0; mi < 4; mi++)
#pragma unroll
        for (int ni = 0; ni < 4; ni++)
#pragma unroll
            for (int r = 0; r < 4; r++) acc[mi][ni][r] = 0.0f;

#define KSTEP(stOfs, ks) do {                                                \
    uint32_t af[4][4], bf[2][4];                                             \
    const uint32_t _ca = ((uint32_t)((ks) * 32) + aHi) ^ xorv;               \
    const uint32_t _cb = ((uint32_t)((ks) * 32) + bHi) ^ xorv;               \
    ldsm4(bf[0], bBase + (stOfs) + _cb);                                     \
    ldsm4(bf[1], bBase + (stOfs) + 2048u + _cb);                             \
    ldsm4(af[0], aBase + (stOfs) + _ca);                                     \
    _Pragma("unroll")                                                        \
    for (int mi = 0; mi < 4; mi++) {                                         \
        if (mi < 3)                                                          \
            ldsm4(af[mi + 1], aBase + (stOfs) + (uint32_t)((mi + 1) * 2048) + _ca); \
        _Pragma("unroll")                                                    \
        for (int ni = 0; ni < 4; ni++) {                                     \
            const int nf = ni >> 1, p = (ni & 1) * 2;                        \
            mma_f16(acc[mi][ni], af[mi], bf[nf][p], bf[nf][p + 1]);          \
        }                                                                    \
    }                                                                        \
} while (0)

    // chunk c body. FULLPH = parity for full[c%3] (0 for c<3, 1 for c>=3).
    // Chunks 0..3 issue chunk c+2 after kstep 0; chunks 1..3 first wait
    // empty[(c+2)%3] (readers of chunk c-1 done). Chunks 0..2 arrive empty.
#define CHUNK0 do { MBAR_WAIT(mbF + 0, 0);                                   \
    KSTEP(0u, 0); ISSUE(2); KSTEP(0u, 1); KSTEP(0u, 2); KSTEP(0u, 3);        \
    MBAR_ARRIVE(mbE + 0); } while (0)
#define CHUNK1 do { MBAR_WAIT(mbF + 8, 0);                                   \
    KSTEP((uint32_t)STAGE_BYTES, 0);                                         \
    MBAR_WAIT(mbE + 0, 0); ISSUE(3);                                         \
    KSTEP((uint32_t)STAGE_BYTES, 1); KSTEP((uint32_t)STAGE_BYTES, 2);        \
    KSTEP((uint32_t)STAGE_BYTES, 3); MBAR_ARRIVE(mbE + 8); } while (0)
#define CHUNK2 do { MBAR_WAIT(mbF + 16, 0);                                  \
    KSTEP((uint32_t)(2*STAGE_BYTES), 0);                                     \
    MBAR_WAIT(mbE + 8, 0); ISSUE(4);                                         \
    KSTEP((uint32_t)(2*STAGE_BYTES), 1); KSTEP((uint32_t)(2*STAGE_BYTES), 2);\
    KSTEP((uint32_t)(2*STAGE_BYTES), 3); MBAR_ARRIVE(mbE + 16); } while (0)
#define CHUNK3 do { MBAR_WAIT(mbF + 0, 1);                                   \
    KSTEP(0u, 0);                                                            \
    MBAR_WAIT(mbE + 16, 0); ISSUE(5);                                        \
    KSTEP(0u, 1); KSTEP(0u, 2); KSTEP(0u, 3); } while (0)
#define CHUNK4 do { MBAR_WAIT(mbF + 8, 1);                                   \
    KSTEP((uint32_t)STAGE_BYTES, 0); KSTEP((uint32_t)STAGE_BYTES, 1);        \
    KSTEP((uint32_t)STAGE_BYTES, 2); KSTEP((uint32_t)STAGE_BYTES, 3); } while (0)
#define CHUNK5 do { MBAR_WAIT(mbF + 16, 1);                                  \
    KSTEP((uint32_t)(2*STAGE_BYTES), 0); KSTEP((uint32_t)(2*STAGE_BYTES), 1);\
    KSTEP((uint32_t)(2*STAGE_BYTES), 2); KSTEP((uint32_t)(2*STAGE_BYTES), 3); } while (0)

    CHUNK0; CHUNK1; CHUNK2; CHUNK3; CHUNK4; CHUNK5;

    // ------------------------- epilogue -------------------------
    float scr[8], ccr[8], w2r[8];
#pragma unroll
    for (int ni = 0; ni < 4; ni++)
#pragma unroll
        for (int j = 0; j < 2; j++) {
            const int k = wn * 32 + ni * 8 + (lane & 3) * 2 + j;
            scr[ni * 2 + j] = sc_s[k];
            ccr[ni * 2 + j] = cc_s[k];
            w2r[ni * 2 + j] = w2_s[k];
        }

#pragma unroll
    for (int mi = 0; mi < 4; mi++) {
#pragma unroll
        for (int h = 0; h < 2; h++) {
            float s = 0.0f;
#pragma unroll
            for (int ni = 0; ni < 4; ni++) {
#pragma unroll
                for (int j = 0; j < 2; j++) {
                    float y = fmaf(acc[mi][ni][h * 2 + j],
                                   scr[ni * 2 + j], ccr[ni * 2 + j]);
                    y = fmaxf(y, 0.01f * y);          // LeakyReLU
                    s = fmaf(y, w2r[ni * 2 + j], s);
                }
            }
            s += __shfl_xor_sync(0xffffffffu, s, 1);
            s += __shfl_xor_sync(0xffffffffu, s, 2);
            if ((lane & 3) == 0) {
                const int row = wm * 64 + mi * 16 + h * 8 + (lane >> 2);
                red[row * 4 + wn] = s;
            }
        }
    }
    __syncthreads();

    if (tid < 128) {
        const float s = red[tid * 4 + 0] + red[tid * 4 + 1]
                      + red[tid * 4 + 2] + red[tid * 4 + 3] + b2[t];
        out[(size_t)(b0 + tid) * T_ + t] = s;
    }
#undef ISSUE
#undef KSTEP
#undef CHUNK0
#undef CHUNK1
#undef CHUNK2
#undef CHUNK3
#undef CHUNK4
#undef CHUNK5
}

// ----------------------------------------------------------------------------
// launch
// ----------------------------------------------------------------------------
extern "C" void kernel_launch(void* const* d_in, const int* in_sizes, int n_in,
                              void* d_out, int out_size)
{
    const float* f     = (const float*)d_in[0];
    const float* W1    = (const float*)d_in[1];
    const float* b1    = (const float*)d_in[2];
    const float* gamma = (const float*)d_in[3];
    const float* beta  = (const float*)d_in[4];
    const float* rmean = (const float*)d_in[5];
    const float* rvar  = (const float*)d_in[6];
    const float* W2    = (const float*)d_in[7];
    const float* b2    = (const float*)d_in[8];
    float* out = (float*)d_out;

    {
        const size_t total4 = (size_t)NF / 4 + (size_t)NW / 4;
        const int blocks = (int)((total4 + 255) / 256);
        split_kernel<<<blocks, 256>>>(f, W1);
    }

    cudaFuncSetAttribute(heads_mma_kernel,
                         cudaFuncAttributeMaxDynamicSharedMemorySize, SMEM_TOTAL);
    dim3 grid(B_ / BM, T_);
    heads_mma_kernel<<<grid, 256, SMEM_TOTAL>>>(b1, gamma, beta, rmean, rvar,
                                                W2, b2, out);
}